// round 15
// baseline (speedup 1.0000x reference)
#include <cuda_runtime.h>
#include <cuda_fp16.h>
#include <cstdint>
#include <math.h>

#define BB   16
#define SS   512
#define DD   768
#define HH   12
#define DNN  64
#define FF   3072
#define LL   6
#define MM   (BB*SS)
#define NQKV 2304

#define SZ_QKV (NQKV*DD)
#define SZ_O   (DD*DD)
#define SZ_W1  (FF*DD)
#define SZ_W2  (DD*FF)
#define OFF_O   SZ_QKV
#define OFF_W1  (OFF_O + SZ_O)
#define OFF_W2  (OFF_W1 + SZ_W1)
#define LAYER_SZ (OFF_W2 + SZ_W2)

// ---------------- scratch ----------------
__device__ __align__(16) float g_h  [MM*DD];
__device__ __align__(16) float g_t  [MM*DD];
__device__ __align__(16) float g_t2 [MM*DD];
__device__ __align__(16) __half g_hhi[(size_t)MM*DD];
__device__ __align__(16) __half g_hlo[(size_t)MM*DD];
__device__ __align__(16) __half g_qkvh[(size_t)MM*NQKV];
__device__ __align__(16) __half g_qkvl[(size_t)MM*NQKV];
__device__ __align__(16) __half g_ohi[(size_t)MM*DD];
__device__ __align__(16) __half g_olo[(size_t)MM*DD];
__device__ __align__(16) __half g_fhi[(size_t)MM*FF];
__device__ __align__(16) __half g_flo[(size_t)MM*FF];
__device__ __align__(16) __half g_Wh [(size_t)LL*LAYER_SZ];
__device__ __align__(16) unsigned char g_mask8[(size_t)BB*SS*SS];

// ======================= PTX helpers =======================
__device__ __forceinline__ uint32_t smem_u32(const void* p) {
    uint32_t a;
    asm("{ .reg .u64 t; cvta.to.shared.u64 t, %1; cvt.u32.u64 %0, t; }" : "=r"(a) : "l"(p));
    return a;
}
#define CP_ASYNC(dst, src) \
    asm volatile("cp.async.cg.shared.global [%0], [%1], 16;" :: "r"(dst), "l"(src) : "memory")
#define CP_COMMIT() asm volatile("cp.async.commit_group;" ::: "memory")
#define CP_WAIT0()  asm volatile("cp.async.wait_group 0;" ::: "memory")

#define LDSM4(r, addr) \
    asm volatile("ldmatrix.sync.aligned.m8n8.x4.shared.b16 {%0,%1,%2,%3}, [%4];" \
        : "=r"((r)[0]), "=r"((r)[1]), "=r"((r)[2]), "=r"((r)[3]) : "r"(addr))
#define LDSM4T(r, addr) \
    asm volatile("ldmatrix.sync.aligned.m8n8.x4.trans.shared.b16 {%0,%1,%2,%3}, [%4];" \
        : "=r"((r)[0]), "=r"((r)[1]), "=r"((r)[2]), "=r"((r)[3]) : "r"(addr))
#define MMA16816(c, a, b) \
    asm volatile("mma.sync.aligned.m16n8k16.row.col.f32.f16.f16.f32 " \
        "{%0,%1,%2,%3},{%4,%5,%6,%7},{%8,%9},{%0,%1,%2,%3};" \
        : "+f"((c)[0]), "+f"((c)[1]), "+f"((c)[2]), "+f"((c)[3]) \
        : "r"((a)[0]), "r"((a)[1]), "r"((a)[2]), "r"((a)[3]), "r"((b)[0]), "r"((b)[1]))

// fast exp on fma pipe
__device__ __forceinline__ float fexp(float x) {
    x = fminf(fmaxf(x, -60.f), 60.f);
    float y = x * 1.4426950408889634f;
    float t = y + 12582912.0f;
    int n = __float_as_int(t) - 0x4B400000;
    float f = y - (t - 12582912.0f);
    float p =       1.3333558e-3f;
    p = fmaf(p, f,  9.6181291e-3f);
    p = fmaf(p, f,  5.5504109e-2f);
    p = fmaf(p, f,  2.4022651e-1f);
    p = fmaf(p, f,  6.9314718e-1f);
    p = fmaf(p, f,  1.0f);
    return __int_as_float(__float_as_int(p) + (n << 23));
}

__device__ __forceinline__ void hsplit2(float v0, float v1, uint32_t& hi, uint32_t& lo) {
    __half2 h = __floats2half2_rn(v0, v1);
    __half2 l = __floats2half2_rn(v0 - __low2float(h), v1 - __high2float(h));
    hi = *(uint32_t*)&h;
    lo = *(uint32_t*)&l;
}

// ======================= tiled transpose -> fp16 =======================
__device__ __forceinline__ void tsplit_body(const float* __restrict__ src,
                                            __half* __restrict__ hi,
                                            int R, int C)
{
    __shared__ float t[32][33];
    int c0 = blockIdx.x*32, r0 = blockIdx.y*32;
    int tx = threadIdx.x & 31, ty = threadIdx.x >> 5;
#pragma unroll
    for (int i = 0; i < 32; i += 8)
        t[ty+i][tx] = src[(size_t)(r0+ty+i)*C + c0+tx];
    __syncthreads();
#pragma unroll
    for (int i = 0; i < 32; i += 8) {
        float v = t[tx][ty+i];
        hi[(size_t)(c0+ty+i)*R + r0+tx] = __float2half(v);
    }
}

__global__ void tsplit(const float* __restrict__ src, __half* __restrict__ hi,
                       int R, int C, size_t sStride, size_t dStride)
{
    int z = blockIdx.z;
    tsplit_body(src + z*sStride, hi + z*dStride, R, C);
}

__global__ void tsplit_qkv(const float* __restrict__ Wq, const float* __restrict__ Wk,
                           const float* __restrict__ Wv)
{
    int z = blockIdx.z;
    int l = z / 36, rem = z % 36, sec = rem / 12, h = rem % 12;
    const float* W = sec==0 ? Wq : (sec==1 ? Wk : Wv);
    const float* src = W + ((size_t)l*HH + h)*DD*DNN;
    size_t dofs = (size_t)l*LAYER_SZ + (size_t)(sec*DD + h*DNN)*DD;
    tsplit_body(src, g_Wh + dofs, DD, DNN);
}

// ---------------- embedding + inline PE + mask conversion (fused) ----------------
#define EMBED_BLKS ((MM*DD+255)/256)
#define MASK_BLKS  ((BB*SS*SS/4+255)/256)

__global__ void embed_mask_kernel(const int* __restrict__ x, const float* __restrict__ emb,
                                  const int* __restrict__ msk)
{
    if (blockIdx.x >= EMBED_BLKS) {
        int i = (blockIdx.x - EMBED_BLKS)*256 + threadIdx.x;
        int4 v = ((const int4*)msk)[i];
        ((uchar4*)g_mask8)[i] = make_uchar4((unsigned char)v.x, (unsigned char)v.y,
                                            (unsigned char)v.z, (unsigned char)v.w);
        return;
    }
    int idx = blockIdx.x*256 + threadIdx.x;
    if (idx >= MM*DD) return;
    int m = idx / DD, d = idx % DD;
    int s = m % SS;
    int tok = x[m];
    const float LOG10000 = 9.210340371976184f;
    int i = d >> 1;
    float pe;
    if ((d & 1) == 0) {
        float freq = expf(-(2.0f*i/DD)*LOG10000);
        pe = sinf(s*freq);
    } else {
        float freq = expf(-(2.0f*(i+1)/DD)*LOG10000);
        pe = cosf(s*freq);
    }
    float v = emb[(size_t)tok*DD + d] + pe;
    g_h[idx] = v;
    __half h = __float2half(v);
    g_hhi[idx] = h;
    g_hlo[idx] = __float2half(v - __half2float(h));
}

// ======================= fp16 2-MMA GEMM, 64-wide k-chunks, 2-stage =======================
#define GTILE 16384               // 128 rows x 128B
#define GSTAGE (3*GTILE)          // 49152
#define GEMM_SMEM (2*GSTAGE)      // 98304

__device__ __forceinline__ uint32_t swz128(int r, int cg) {
    return (uint32_t)(r*128 + ((cg ^ (r & 7)) << 4));
}

// EPI 1: relu(+bias)->fp16 hi/lo | 3: +qkv-bias->fp16 (lo only for Q cols) | 4: split-K fp32 partial
template<int EPI>
__global__ void __launch_bounds__(256, 2)
gemm_mma(const __half* __restrict__ Ahi, const __half* __restrict__ Alo,
         const __half* __restrict__ Bh,
         const float* __restrict__ bias, const float* __restrict__ biasK,
         const float* __restrict__ biasV,
         float* __restrict__ outf, float* __restrict__ outf2,
         __half* __restrict__ outhi, __half* __restrict__ outlo,
         int K, int Ndim)
{
    extern __shared__ char sm[];
    int tid = threadIdx.x, wid = tid >> 5, lid = tid & 31;
    int m0 = blockIdx.y * 128, c0 = blockIdx.x * 128;
    int warp_m = (wid & 3) * 32, warp_n = (wid >> 2) * 64;

    const __half *pAh = Ahi, *pAl = Alo, *pB = Bh;
    float* pout = outf;
    int NCH;
    if (EPI == 4) {
        int half_k = K >> 1;
        int kofs = blockIdx.z * half_k;
        pAh += kofs; pAl += kofs; pB += kofs;
        if (blockIdx.z) pout = outf2;
        NCH = half_k >> 6;
    } else {
        NCH = K >> 6;
    }

    float c[2][8][4];
#pragma unroll
    for (int i=0;i<2;i++)
#pragma unroll
        for (int j=0;j<8;j++)
#pragma unroll
            for (int q=0;q<4;q++) c[i][j][q] = 0.f;

    auto load_chunk = [&](int ci, int st) {
        int k0 = ci << 6;
        char* base = sm + st * GSTAGE;
#pragma unroll
        for (int i = 0; i < 12; i++) {
            int seg = tid + i*256;
            int tl  = seg >> 10;
            int rem = seg & 1023;
            int r   = rem >> 3, cg = rem & 7;
            const __half* src;
            if      (tl == 0) src = pAh + (size_t)(m0 + r)*K + k0 + cg*8;
            else if (tl == 1) src = pAl + (size_t)(m0 + r)*K + k0 + cg*8;
            else              src = pB  + (size_t)(c0 + r)*K + k0 + cg*8;
            CP_ASYNC(smem_u32(base + tl*GTILE + swz128(r, cg)), src);
        }
        CP_COMMIT();
    };

    load_chunk(0, 0);

    for (int ci = 0; ci < NCH; ci++) {
        int st = ci & 1;
        CP_WAIT0();
        __syncthreads();
        if (ci + 1 < NCH) load_chunk(ci + 1, st ^ 1);

        uint32_t base = smem_u32(sm + st * GSTAGE);
#pragma unroll
        for (int ks = 0; ks < 4; ks++) {
            uint32_t ah[2][4], al[2][4], bh[8][2];
            int acg = ks*2 + (lid >> 4);
            int bcg = ks*2 + ((lid >> 3) & 1);
#pragma unroll
            for (int mt = 0; mt < 2; mt++) {
                int r = warp_m + mt*16 + (lid & 15);
                LDSM4(ah[mt], base + 0*GTILE + swz128(r, acg));
                LDSM4(al[mt], base + 1*GTILE + swz128(r, acg));
            }
#pragma unroll
            for (int np = 0; np < 4; np++) {
                int r = warp_n + np*16 + ((lid >> 4) << 3) + (lid & 7);
                uint32_t t4[4];
                LDSM4(t4, base + 2*GTILE + swz128(r, bcg));
                bh[np*2][0]=t4[0]; bh[np*2][1]=t4[1]; bh[np*2+1][0]=t4[2]; bh[np*2+1][1]=t4[3];
            }
#pragma unroll
            for (int mt = 0; mt < 2; mt++)
#pragma unroll
                for (int nt = 0; nt < 8; nt++) {
                    MMA16816(c[mt][nt], ah[mt], bh[nt]);
                    MMA16816(c[mt][nt], al[mt], bh[nt]);
                }
        }
    }

    const float* bptr = bias;
    int cofs = 0;
    bool wantLo = true;
    if (EPI == 3) {
        int sec = (c0 >= 1536) ? 2 : (c0 >= 768 ? 1 : 0);
        bptr = (sec == 0) ? bias : (sec == 1 ? biasK : biasV);
        cofs = sec * 768;
        wantLo = (sec == 0);
    }
    int g = lid >> 2, t2 = (lid & 3) * 2;
#pragma unroll
    for (int mt = 0; mt < 2; mt++) {
#pragma unroll
        for (int half_i = 0; half_i < 2; half_i++) {
            long m = m0 + warp_m + mt*16 + g + half_i*8;
#pragma unroll
            for (int nt = 0; nt < 8; nt++) {
                int col = c0 + warp_n + nt*8 + t2;
                if (EPI == 4) {
                    *(float2*)(pout + m*(long)Ndim + col) =
                        make_float2(c[mt][nt][half_i*2+0], c[mt][nt][half_i*2+1]);
                } else {
                    float v0 = c[mt][nt][half_i*2+0] + bptr[col - cofs];
                    float v1 = c[mt][nt][half_i*2+1] + bptr[col - cofs + 1];
                    if (EPI == 1) { v0 = fmaxf(v0, 0.f); v1 = fmaxf(v1, 0.f); }
                    uint32_t hp, lp;
                    hsplit2(v0, v1, hp, lp);
                    *(uint32_t*)(outhi + m*(long)Ndim + col) = hp;
                    if (EPI != 3 || wantLo)
                        *(uint32_t*)(outlo + m*(long)Ndim + col) = lp;
                }
            }
        }
    }
}

// ======================= fp16 attention, x4-ldmatrix batched, 64-row stages, 2 CTA/SM =======================
#define AT_ST0 36864
#define AT_KH 0
#define AT_VH 9216
#define AT_MS 18432
#define AT_STAGE 26624
#define AT_SMEM (AT_ST0 + 2*AT_STAGE)   // 90112

__global__ void __launch_bounds__(256, 2)
attn_mma(const __half* __restrict__ qvh, const __half* __restrict__ qvl,
         const unsigned char* __restrict__ mask8,
         __half* __restrict__ ohi, __half* __restrict__ olo)
{
    extern __shared__ char smn[];
    int tid = threadIdx.x, wid = tid >> 5, lid = tid & 31;
    int bh = blockIdx.x;
    int b = bh / HH, h = bh % HH;
    int sq0 = blockIdx.y * 128;
    const size_t rowbase = (size_t)b * SS;
    int g = lid >> 2, t2 = lid & 3;
    int l15 = lid & 15, l8 = lid & 7;
    int selK = (lid >> 3) & 1;      // k-half for K b-frags
    int qq = lid >> 4;              // 0/1: which tile of the x4 pair this lane addresses

    // prologue: Q (hi/lo), 128 rows x 128B, stride 144
#pragma unroll
    for (int i = 0; i < 8; i++) {
        int s = tid + i*256;
        int arr = s >> 10, rem = s & 1023;
        int r = rem >> 3, cg = rem & 7;
        const __half* src = (arr ? qvl : qvh) +
            (rowbase + sq0 + r)*(size_t)NQKV + h*DNN + cg*8;
        CP_ASYNC(smem_u32(smn + arr*18432 + r*144 + cg*16), src);
    }

    auto load_kv = [&](int kci, int st) {
        int kc = kci * 64;
        char* base = smn + AT_ST0 + st*AT_STAGE;
#pragma unroll
        for (int i = 0; i < 4; i++) {
            int s = tid + i*256;
            int tl = s >> 9, rem = s & 511;
            int r = rem >> 3, cg = rem & 7;
            size_t off = (rowbase + kc + r)*(size_t)NQKV + h*DNN + cg*8;
            const __half* src = qvh + off + (tl ? 2*DD : DD);
            CP_ASYNC(smem_u32(base + tl*9216 + r*144 + cg*16), src);
        }
#pragma unroll
        for (int i = 0; i < 2; i++) {
            int s = tid + i*256;
            int r = s >> 2, seg = s & 3;
            CP_ASYNC(smem_u32(base + AT_MS + r*64 + seg*16),
                     mask8 + (rowbase + sq0 + r)*(size_t)SS + kc + seg*16);
        }
        CP_COMMIT();
    };

    load_kv(0, 0);

    uint32_t qfh[4][4], qfl[4][4];
    float o[8][4];
#pragma unroll
    for (int nt = 0; nt < 8; nt++)
#pragma unroll
        for (int q = 0; q < 4; q++) o[nt][q] = 0.f;
    float rs0 = 0.f, rs1 = 0.f;

    for (int ci = 0; ci < 8; ci++) {
        int st = ci & 1;
        CP_WAIT0();
        __syncthreads();
        if (ci == 0) {
            uint32_t qb = smem_u32(smn);
#pragma unroll
            for (int kg = 0; kg < 4; kg++) {
                uint32_t qa = qb + (wid*16 + l15)*144 + kg*32 + (lid >> 4)*16;
                LDSM4(qfh[kg], qa);
                LDSM4(qfl[kg], qa + 18432);
            }
        }
        if (ci + 1 < 8) load_kv(ci + 1, st ^ 1);

        uint32_t sb = smem_u32(smn + AT_ST0 + st*AT_STAGE);
        const unsigned char* msm = (const unsigned char*)(smn + AT_ST0 + st*AT_STAGE + AT_MS);

#pragma unroll
        for (int h2 = 0; h2 < 2; h2++) {
            int rof = h2 * 32;
            float s[4][4];
#pragma unroll
            for (int nt = 0; nt < 4; nt++)
#pragma unroll
                for (int q = 0; q < 4; q++) s[nt][q] = 0.f;

            // S = Q K^T — x4 ldmatrix serves nt and nt+1 together
#pragma unroll
            for (int kg = 0; kg < 4; kg++) {
#pragma unroll
                for (int nt = 0; nt < 4; nt += 2) {
                    uint32_t t4[4];
                    uint32_t ka = sb + (rof + (nt + qq)*8 + l8)*144 + kg*32 + selK*16;
                    LDSM4(t4, ka + AT_KH);
                    uint32_t b0[2] = {t4[0], t4[1]};
                    uint32_t b1[2] = {t4[2], t4[3]};
                    MMA16816(s[nt],   qfh[kg], b0);
                    MMA16816(s[nt],   qfl[kg], b0);
                    MMA16816(s[nt+1], qfh[kg], b1);
                    MMA16816(s[nt+1], qfl[kg], b1);
                }
            }

            // softmax numerator + pack P
            const unsigned char* mr0 = msm + (wid*16 + g)*64 + rof;
            const unsigned char* mr1 = mr0 + 8*64;
            uint32_t aPh[2][4], aPl[2][4];
#pragma unroll
            for (int nt = 0; nt < 4; nt++) {
                uchar2 m0 = *(const uchar2*)(mr0 + nt*8 + t2*2);
                uchar2 m1 = *(const uchar2*)(mr1 + nt*8 + t2*2);
                float p0 = m0.x ? 0.f : fexp(s[nt][0]*0.125f);
                float p1 = m0.y ? 0.f : fexp(s[nt][1]*0.125f);
                float p2 = m1.x ? 0.f : fexp(s[nt][2]*0.125f);
                float p3 = m1.y ? 0.f : fexp(s[nt][3]*0.125f);
                rs0 += p0 + p1;
                rs1 += p2 + p3;
                int kg = nt >> 1, sub = (nt & 1)*2;
                hsplit2(p0, p1, aPh[kg][sub],   aPl[kg][sub]);
                hsplit2(p2, p3, aPh[kg][sub+1], aPl[kg][sub+1]);
            }

            // O += P V — x4 trans ldmatrix serves nt and nt+1 together
#pragma unroll
            for (int kg = 0; kg < 2; kg++) {
#pragma unroll
                for (int nt = 0; nt < 8; nt += 2) {
                    uint32_t t4[4];
                    uint32_t va = sb + AT_VH + (rof + kg*16 + l15)*144 + (nt + qq)*16;
                    LDSM4T(t4, va);
                    uint32_t v0[2] = {t4[0], t4[1]};
                    uint32_t v1[2] = {t4[2], t4[3]};
                    MMA16816(o[nt],   aPh[kg], v0);
                    MMA16816(o[nt],   aPl[kg], v0);
                    MMA16816(o[nt+1], aPh[kg], v1);
                    MMA16816(o[nt+1], aPl[kg], v1);
                }
            }
        }
    }

    rs0 += __shfl_xor_sync(0xFFFFFFFFu, rs0, 1);
    rs0 += __shfl_xor_sync(0xFFFFFFFFu, rs0, 2);
    rs1 += __shfl_xor_sync(0xFFFFFFFFu, rs1, 1);
    rs1 += __shfl_xor_sync(0xFFFFFFFFu, rs1, 2);
    float inv0 = 1.f / rs0, inv1 = 1.f / rs1;

    long r0 = rowbase + sq0 + wid*16 + g;
    int colb = h*DNN + t2*2;
#pragma unroll
    for (int nt = 0; nt < 8; nt++) {
        int col = colb + nt*8;
        uint32_t hp0, lp0, hp1, lp1;
        hsplit2(o[nt][0]*inv0, o[nt][1]*inv0, hp0, lp0);
        hsplit2(o[nt][2]*inv1, o[nt][3]*inv1, hp1, lp1);
        *(uint32_t*)(ohi + r0*DD + col)     = hp0;
        *(uint32_t*)(olo + r0*DD + col)     = lp0;
        *(uint32_t*)(ohi + (r0+8)*DD + col) = hp1;
        *(uint32_t*)(olo + (r0+8)*DD + col) = lp1;
    }
}

// ---------------- fused split-K-reduce + layernorm (warp-per-row) ----------------
__global__ void __launch_bounds__(256)
ln2_kernel(const float* __restrict__ p1, const float* __restrict__ p2,
           const float* __restrict__ res, const float* __restrict__ bias,
           const float* __restrict__ g, const float* __restrict__ be,
           float* __restrict__ out,
           __half* __restrict__ ohi, __half* __restrict__ olo)
{
    int row = blockIdx.x*8 + (threadIdx.x >> 5);
    int lane = threadIdx.x & 31;
    size_t base = (size_t)row*DD;

    float v[24];
    float s = 0.f, sq = 0.f;
#pragma unroll
    for (int i = 0; i < 6; i++) {
        int col = lane*4 + i*128;
        float4 a  = *(const float4*)(p1  + base + col);
        float4 b  = *(const float4*)(p2  + base + col);
        float4 r  = *(const float4*)(res + base + col);
        float4 bi = *(const float4*)(bias + col);
        float x0 = a.x + b.x + r.x + bi.x;
        float x1 = a.y + b.y + r.y + bi.y;
        float x2 = a.z + b.z + r.z + bi.z;
        float x3 = a.w + b.w + r.w + bi.w;
        v[i*4+0]=x0; v[i*4+1]=x1; v[i*4+2]=x2; v[i*4+3]=x3;
        s += (x0+x1) + (x2+x3);
        sq += (x0*x0 + x1*x1) + (x2*x2 + x3*x3);
    }
#pragma unroll
    for (int o = 16; o > 0; o >>= 1) {
        s  += __shfl_xor_sync(0xFFFFFFFFu, s,  o);
        sq += __shfl_xor_sync(0xFFFFFFFFu, sq, o);
    }
    float mean = s * (1.0f/768.0f);
    float var  = sq * (1.0f/768.0f) - mean*mean;
    float rstd = rsqrtf(var + 1e-5f);

#pragma unroll
    for (int i = 0; i < 6; i++) {
        int col = lane*4 + i*128;
        float4 gg = *(const float4*)(g  + col);
        float4 bb = *(const float4*)(be + col);
        float y0 = (v[i*4+0]-mean)*rstd*gg.x + bb.x;
        float y1 = (v[i*4+1]-mean)*rstd*gg.y + bb.y;
        float y2 = (v[i*4+2]-mean)*rstd*gg.z + bb.z;
        float y3 = (v[i*4+3]-mean)*rstd*gg.w + bb.w;
        *(float4*)(out + base + col) = make_float4(y0, y1, y2, y3);
        uint2 hp, lp;
        hsplit2(y0, y1, hp.x, lp.x);
        hsplit2(y2, y3, hp.y, lp.y);
        *(uint2*)(ohi + base + col) = hp;
        *(uint2*)(olo + base + col) = lp;
    }
}

// ---------------- host ----------------
extern "C" void kernel_launch(void* const* d_in, const int* in_sizes, int n_in,
                              void* d_out, int out_size)
{
    const int*   x    = (const int*)  d_in[0];
    const int*   pmsk = (const int*)  d_in[1];
    const float* emb  = (const float*)d_in[2];
    const float* Wq   = (const float*)d_in[3];
    const float* bq   = (const float*)d_in[4];
    const float* Wk   = (const float*)d_in[5];
    const float* bk   = (const float*)d_in[6];
    const float* Wv   = (const float*)d_in[7];
    const float* bv   = (const float*)d_in[8];
    const float* Wo   = (const float*)d_in[9];
    const float* bo   = (const float*)d_in[10];
    const float* W1   = (const float*)d_in[11];
    const float* b1   = (const float*)d_in[12];
    const float* W2   = (const float*)d_in[13];
    const float* b2   = (const float*)d_in[14];
    const float* g1   = (const float*)d_in[15];
    const float* be1  = (const float*)d_in[16];
    const float* g2   = (const float*)d_in[17];
    const float* be2  = (const float*)d_in[18];
    float* outp = (float*)d_out;

    float *hb, *tb, *tb2;
    __half *hhi, *hlo, *qkvh, *qkvl, *ohi, *olo, *fhi, *flo, *wh;
    unsigned char* m8;
    cudaGetSymbolAddress((void**)&hb,    g_h);
    cudaGetSymbolAddress((void**)&tb,    g_t);
    cudaGetSymbolAddress((void**)&tb2,   g_t2);
    cudaGetSymbolAddress((void**)&hhi,   g_hhi);
    cudaGetSymbolAddress((void**)&hlo,   g_hlo);
    cudaGetSymbolAddress((void**)&qkvh,  g_qkvh);
    cudaGetSymbolAddress((void**)&qkvl,  g_qkvl);
    cudaGetSymbolAddress((void**)&ohi,   g_ohi);
    cudaGetSymbolAddress((void**)&olo,   g_olo);
    cudaGetSymbolAddress((void**)&fhi,   g_fhi);
    cudaGetSymbolAddress((void**)&flo,   g_flo);
    cudaGetSymbolAddress((void**)&wh,    g_Wh);
    cudaGetSymbolAddress((void**)&m8,    g_mask8);

    cudaFuncSetAttribute(gemm_mma<1>, cudaFuncAttributeMaxDynamicSharedMemorySize, GEMM_SMEM);
    cudaFuncSetAttribute(gemm_mma<3>, cudaFuncAttributeMaxDynamicSharedMemorySize, GEMM_SMEM);
    cudaFuncSetAttribute(gemm_mma<4>, cudaFuncAttributeMaxDynamicSharedMemorySize, GEMM_SMEM);
    cudaFuncSetAttribute(attn_mma,    cudaFuncAttributeMaxDynamicSharedMemorySize, AT_SMEM);

    dim3 gQKV(NQKV/128, MM/128);
    dim3 gSplit(DD/128, MM/128, 2);
    dim3 gF1 (FF/128,   MM/128);
    dim3 gAttn(BB*HH, SS/128);

    tsplit_qkv<<<dim3(2, 24, LL*36), 256>>>(Wq, Wk, Wv);
    embed_mask_kernel<<<EMBED_BLKS + MASK_BLKS, 256>>>(x, emb, pmsk);

    for (int l = 0; l < LL; l++) {
        const __half* wl = wh + (size_t)l*LAYER_SZ;

        gemm_mma<3><<<gQKV, 256, GEMM_SMEM>>>(hhi, hlo, wl,
            bq + l*DD, bk + l*DD, bv + l*DD,
            nullptr, nullptr, qkvh, qkvl, DD, NQKV);

        attn_mma<<<gAttn, 256, AT_SMEM>>>(qkvh, qkvl, m8, ohi, olo);

        if (l == 0)
            tsplit<<<dim3(24, 24, LL), 256>>>(Wo, wh + OFF_O,
                DD, DD, (size_t)DD*DD, (size_t)LAYER_SZ);

        gemm_mma<4><<<gSplit, 256, GEMM_SMEM>>>(ohi, olo, wl + OFF_O,
            nullptr, nullptr, nullptr, tb, tb2, nullptr, nullptr, DD, DD);

        ln2_kernel<<<MM/8, 256>>>(tb, tb2, hb, bo + l*DD,
                                  g1 + l*DD, be1 + l*DD, hb, hhi, hlo);

        if (l == 0)
            tsplit<<<dim3(96, 24, LL), 256>>>(W1, wh + OFF_W1,
                DD, FF, (size_t)DD*FF, (size_t)LAYER_SZ);

        gemm_mma<1><<<gF1, 256, GEMM_SMEM>>>(hhi, hlo, wl + OFF_W1,
            b1 + l*FF, nullptr, nullptr, nullptr, nullptr, fhi, flo, DD, FF);

        if (l == 0)
            tsplit<<<dim3(24, 96, LL), 256>>>(W2, wh + OFF_W2,
                FF, DD, (size_t)FF*DD, (size_t)LAYER_SZ);

        gemm_mma<4><<<gSplit, 256, GEMM_SMEM>>>(fhi, flo, wl + OFF_W2,
            nullptr, nullptr, nullptr, tb, tb2, nullptr, nullptr, FF, DD);

        float* lnOut = (l == LL-1) ? outp : hb;
        ln2_kernel<<<MM/8, 256>>>(tb, tb2, hb, b2 + l*DD,
                                  g2 + l*DD, be2 + l*DD, lnOut, hhi, hlo);
    }
}

// round 16
// speedup vs baseline: 1.0549x; 1.0549x over previous
#include <cuda_runtime.h>
#include <cuda_fp16.h>
#include <cstdint>
#include <math.h>

#define BB   16
#define SS   512
#define DD   768
#define HH   12
#define DNN  64
#define FF   3072
#define LL   6
#define MM   (BB*SS)
#define NQKV 2304

#define SZ_QKV (NQKV*DD)
#define SZ_O   (DD*DD)
#define SZ_W1  (FF*DD)
#define SZ_W2  (DD*FF)
#define OFF_O   SZ_QKV
#define OFF_W1  (OFF_O + SZ_O)
#define OFF_W2  (OFF_W1 + SZ_W1)
#define LAYER_SZ (OFF_W2 + SZ_W2)

// ---------------- scratch ----------------
__device__ __align__(16) float g_h  [MM*DD];
__device__ __align__(16) float g_t  [MM*DD];
__device__ __align__(16) float g_t2 [MM*DD];
__device__ __align__(16) __half g_hhi[(size_t)MM*DD];
__device__ __align__(16) __half g_hlo[(size_t)MM*DD];
__device__ __align__(16) __half g_qkvh[(size_t)MM*NQKV];
__device__ __align__(16) __half g_ohi[(size_t)MM*DD];
__device__ __align__(16) __half g_olo[(size_t)MM*DD];
__device__ __align__(16) __half g_fhi[(size_t)MM*FF];
__device__ __align__(16) __half g_flo[(size_t)MM*FF];
__device__ __align__(16) __half g_Wh [(size_t)LL*LAYER_SZ];
__device__ __align__(16) unsigned char g_mask8[(size_t)BB*SS*SS];

// ======================= PTX helpers =======================
__device__ __forceinline__ uint32_t smem_u32(const void* p) {
    uint32_t a;
    asm("{ .reg .u64 t; cvta.to.shared.u64 t, %1; cvt.u32.u64 %0, t; }" : "=r"(a) : "l"(p));
    return a;
}
#define CP_ASYNC(dst, src) \
    asm volatile("cp.async.cg.shared.global [%0], [%1], 16;" :: "r"(dst), "l"(src) : "memory")
#define CP_COMMIT() asm volatile("cp.async.commit_group;" ::: "memory")
#define CP_WAIT0()  asm volatile("cp.async.wait_group 0;" ::: "memory")

#define LDSM4(r, addr) \
    asm volatile("ldmatrix.sync.aligned.m8n8.x4.shared.b16 {%0,%1,%2,%3}, [%4];" \
        : "=r"((r)[0]), "=r"((r)[1]), "=r"((r)[2]), "=r"((r)[3]) : "r"(addr))
#define LDSM4T(r, addr) \
    asm volatile("ldmatrix.sync.aligned.m8n8.x4.trans.shared.b16 {%0,%1,%2,%3}, [%4];" \
        : "=r"((r)[0]), "=r"((r)[1]), "=r"((r)[2]), "=r"((r)[3]) : "r"(addr))
#define MMA16816(c, a, b) \
    asm volatile("mma.sync.aligned.m16n8k16.row.col.f32.f16.f16.f32 " \
        "{%0,%1,%2,%3},{%4,%5,%6,%7},{%8,%9},{%0,%1,%2,%3};" \
        : "+f"((c)[0]), "+f"((c)[1]), "+f"((c)[2]), "+f"((c)[3]) \
        : "r"((a)[0]), "r"((a)[1]), "r"((a)[2]), "r"((a)[3]), "r"((b)[0]), "r"((b)[1]))

// fast exp on fma pipe
__device__ __forceinline__ float fexp(float x) {
    x = fminf(fmaxf(x, -60.f), 60.f);
    float y = x * 1.4426950408889634f;
    float t = y + 12582912.0f;
    int n = __float_as_int(t) - 0x4B400000;
    float f = y - (t - 12582912.0f);
    float p =       1.3333558e-3f;
    p = fmaf(p, f,  9.6181291e-3f);
    p = fmaf(p, f,  5.5504109e-2f);
    p = fmaf(p, f,  2.4022651e-1f);
    p = fmaf(p, f,  6.9314718e-1f);
    p = fmaf(p, f,  1.0f);
    return __int_as_float(__float_as_int(p) + (n << 23));
}

__device__ __forceinline__ void hsplit2(float v0, float v1, uint32_t& hi, uint32_t& lo) {
    __half2 h = __floats2half2_rn(v0, v1);
    __half2 l = __floats2half2_rn(v0 - __low2float(h), v1 - __high2float(h));
    hi = *(uint32_t*)&h;
    lo = *(uint32_t*)&l;
}

// ======================= tiled transpose -> fp16 =======================
__device__ __forceinline__ void tsplit_body(const float* __restrict__ src,
                                            __half* __restrict__ hi,
                                            int R, int C)
{
    __shared__ float t[32][33];
    int c0 = blockIdx.x*32, r0 = blockIdx.y*32;
    int tx = threadIdx.x & 31, ty = threadIdx.x >> 5;
#pragma unroll
    for (int i = 0; i < 32; i += 8)
        t[ty+i][tx] = src[(size_t)(r0+ty+i)*C + c0+tx];
    __syncthreads();
#pragma unroll
    for (int i = 0; i < 32; i += 8) {
        float v = t[tx][ty+i];
        hi[(size_t)(c0+ty+i)*R + r0+tx] = __float2half(v);
    }
}

__global__ void tsplit(const float* __restrict__ src, __half* __restrict__ hi,
                       int R, int C, size_t sStride, size_t dStride)
{
    int z = blockIdx.z;
    tsplit_body(src + z*sStride, hi + z*dStride, R, C);
}

__global__ void tsplit_qkv(const float* __restrict__ Wq, const float* __restrict__ Wk,
                           const float* __restrict__ Wv)
{
    int z = blockIdx.z;
    int l = z / 36, rem = z % 36, sec = rem / 12, h = rem % 12;
    const float* W = sec==0 ? Wq : (sec==1 ? Wk : Wv);
    const float* src = W + ((size_t)l*HH + h)*DD*DNN;
    size_t dofs = (size_t)l*LAYER_SZ + (size_t)(sec*DD + h*DNN)*DD;
    tsplit_body(src, g_Wh + dofs, DD, DNN);
}

// ---------------- embedding + inline PE + mask conversion (fused) ----------------
#define EMBED_BLKS ((MM*DD+255)/256)
#define MASK_BLKS  ((BB*SS*SS/4+255)/256)

__global__ void embed_mask_kernel(const int* __restrict__ x, const float* __restrict__ emb,
                                  const int* __restrict__ msk)
{
    if (blockIdx.x >= EMBED_BLKS) {
        int i = (blockIdx.x - EMBED_BLKS)*256 + threadIdx.x;
        int4 v = ((const int4*)msk)[i];
        ((uchar4*)g_mask8)[i] = make_uchar4((unsigned char)v.x, (unsigned char)v.y,
                                            (unsigned char)v.z, (unsigned char)v.w);
        return;
    }
    int idx = blockIdx.x*256 + threadIdx.x;
    if (idx >= MM*DD) return;
    int m = idx / DD, d = idx % DD;
    int s = m % SS;
    int tok = x[m];
    const float LOG10000 = 9.210340371976184f;
    int i = d >> 1;
    float pe;
    if ((d & 1) == 0) {
        float freq = expf(-(2.0f*i/DD)*LOG10000);
        pe = sinf(s*freq);
    } else {
        float freq = expf(-(2.0f*(i+1)/DD)*LOG10000);
        pe = cosf(s*freq);
    }
    float v = emb[(size_t)tok*DD + d] + pe;
    g_h[idx] = v;
    __half h = __float2half(v);
    g_hhi[idx] = h;
    g_hlo[idx] = __float2half(v - __half2float(h));
}

// ======================= fp16 2-MMA GEMM, 64-wide k-chunks, 2-stage =======================
#define GTILE 16384
#define GSTAGE (3*GTILE)
#define GEMM_SMEM (2*GSTAGE)

__device__ __forceinline__ uint32_t swz128(int r, int cg) {
    return (uint32_t)(r*128 + ((cg ^ (r & 7)) << 4));
}

// EPI 1: relu(+bias)->fp16 hi/lo | 3: +qkv-bias->fp16 hi only | 4: split-K fp32 partial
template<int EPI>
__global__ void __launch_bounds__(256, 2)
gemm_mma(const __half* __restrict__ Ahi, const __half* __restrict__ Alo,
         const __half* __restrict__ Bh,
         const float* __restrict__ bias, const float* __restrict__ biasK,
         const float* __restrict__ biasV,
         float* __restrict__ outf, float* __restrict__ outf2,
         __half* __restrict__ outhi, __half* __restrict__ outlo,
         int K, int Ndim)
{
    extern __shared__ char sm[];
    int tid = threadIdx.x, wid = tid >> 5, lid = tid & 31;
    int m0 = blockIdx.y * 128, c0 = blockIdx.x * 128;
    int warp_m = (wid & 3) * 32, warp_n = (wid >> 2) * 64;

    const __half *pAh = Ahi, *pAl = Alo, *pB = Bh;
    float* pout = outf;
    int NCH;
    if (EPI == 4) {
        int half_k = K >> 1;
        int kofs = blockIdx.z * half_k;
        pAh += kofs; pAl += kofs; pB += kofs;
        if (blockIdx.z) pout = outf2;
        NCH = half_k >> 6;
    } else {
        NCH = K >> 6;
    }

    float c[2][8][4];
#pragma unroll
    for (int i=0;i<2;i++)
#pragma unroll
        for (int j=0;j<8;j++)
#pragma unroll
            for (int q=0;q<4;q++) c[i][j][q] = 0.f;

    auto load_chunk = [&](int ci, int st) {
        int k0 = ci << 6;
        char* base = sm + st * GSTAGE;
#pragma unroll
        for (int i = 0; i < 12; i++) {
            int seg = tid + i*256;
            int tl  = seg >> 10;
            int rem = seg & 1023;
            int r   = rem >> 3, cg = rem & 7;
            const __half* src;
            if      (tl == 0) src = pAh + (size_t)(m0 + r)*K + k0 + cg*8;
            else if (tl == 1) src = pAl + (size_t)(m0 + r)*K + k0 + cg*8;
            else              src = pB  + (size_t)(c0 + r)*K + k0 + cg*8;
            CP_ASYNC(smem_u32(base + tl*GTILE + swz128(r, cg)), src);
        }
        CP_COMMIT();
    };

    load_chunk(0, 0);

    for (int ci = 0; ci < NCH; ci++) {
        int st = ci & 1;
        CP_WAIT0();
        __syncthreads();
        if (ci + 1 < NCH) load_chunk(ci + 1, st ^ 1);

        uint32_t base = smem_u32(sm + st * GSTAGE);
#pragma unroll
        for (int ks = 0; ks < 4; ks++) {
            uint32_t ah[2][4], al[2][4], bh[8][2];
            int acg = ks*2 + (lid >> 4);
            int bcg = ks*2 + ((lid >> 3) & 1);
#pragma unroll
            for (int mt = 0; mt < 2; mt++) {
                int r = warp_m + mt*16 + (lid & 15);
                LDSM4(ah[mt], base + 0*GTILE + swz128(r, acg));
                LDSM4(al[mt], base + 1*GTILE + swz128(r, acg));
            }
#pragma unroll
            for (int np = 0; np < 4; np++) {
                int r = warp_n + np*16 + ((lid >> 4) << 3) + (lid & 7);
                uint32_t t4[4];
                LDSM4(t4, base + 2*GTILE + swz128(r, bcg));
                bh[np*2][0]=t4[0]; bh[np*2][1]=t4[1]; bh[np*2+1][0]=t4[2]; bh[np*2+1][1]=t4[3];
            }
#pragma unroll
            for (int mt = 0; mt < 2; mt++)
#pragma unroll
                for (int nt = 0; nt < 8; nt++) {
                    MMA16816(c[mt][nt], ah[mt], bh[nt]);
                    MMA16816(c[mt][nt], al[mt], bh[nt]);
                }
        }
    }

    const float* bptr = bias;
    int cofs = 0;
    if (EPI == 3) {
        int sec = (c0 >= 1536) ? 2 : (c0 >= 768 ? 1 : 0);
        bptr = (sec == 0) ? bias : (sec == 1 ? biasK : biasV);
        cofs = sec * 768;
    }
    int g = lid >> 2, t2 = (lid & 3) * 2;
#pragma unroll
    for (int mt = 0; mt < 2; mt++) {
#pragma unroll
        for (int half_i = 0; half_i < 2; half_i++) {
            long m = m0 + warp_m + mt*16 + g + half_i*8;
#pragma unroll
            for (int nt = 0; nt < 8; nt++) {
                int col = c0 + warp_n + nt*8 + t2;
                if (EPI == 4) {
                    *(float2*)(pout + m*(long)Ndim + col) =
                        make_float2(c[mt][nt][half_i*2+0], c[mt][nt][half_i*2+1]);
                } else if (EPI == 3) {
                    float v0 = c[mt][nt][half_i*2+0] + bptr[col - cofs];
                    float v1 = c[mt][nt][half_i*2+1] + bptr[col - cofs + 1];
                    __half2 hp = __floats2half2_rn(v0, v1);
                    *(uint32_t*)(outhi + m*(long)Ndim + col) = *(uint32_t*)&hp;
                } else {
                    float v0 = c[mt][nt][half_i*2+0] + bptr[col];
                    float v1 = c[mt][nt][half_i*2+1] + bptr[col + 1];
                    v0 = fmaxf(v0, 0.f); v1 = fmaxf(v1, 0.f);
                    uint32_t hp, lp;
                    hsplit2(v0, v1, hp, lp);
                    *(uint32_t*)(outhi + m*(long)Ndim + col) = hp;
                    *(uint32_t*)(outlo + m*(long)Ndim + col) = lp;
                }
            }
        }
    }
}

// ======================= fp16 attention, single-plane Q/K/V/P, 64-row stages, 2 CTA/SM =======================
#define AT_ST0 18432
#define AT_KH 0
#define AT_VH 9216
#define AT_MS 18432
#define AT_STAGE 26624
#define AT_SMEM (AT_ST0 + 2*AT_STAGE)   // 71680

__global__ void __launch_bounds__(256, 2)
attn_mma(const __half* __restrict__ qvh,
         const unsigned char* __restrict__ mask8,
         __half* __restrict__ ohi, __half* __restrict__ olo)
{
    extern __shared__ char smn[];
    int tid = threadIdx.x, wid = tid >> 5, lid = tid & 31;
    int bh = blockIdx.x;
    int b = bh / HH, h = bh % HH;
    int sq0 = blockIdx.y * 128;
    const size_t rowbase = (size_t)b * SS;
    int g = lid >> 2, t2 = lid & 3;
    int l15 = lid & 15, l8 = lid & 7;
    int selK = (lid >> 3) & 1;
    int qq = lid >> 4;

    // prologue: Q hi, 128 rows x 128B, stride 144
#pragma unroll
    for (int i = 0; i < 4; i++) {
        int s = tid + i*256;
        int r = s >> 3, cg = s & 7;
        const __half* src = qvh + (rowbase + sq0 + r)*(size_t)NQKV + h*DNN + cg*8;
        CP_ASYNC(smem_u32(smn + r*144 + cg*16), src);
    }

    auto load_kv = [&](int kci, int st) {
        int kc = kci * 64;
        char* base = smn + AT_ST0 + st*AT_STAGE;
#pragma unroll
        for (int i = 0; i < 4; i++) {
            int s = tid + i*256;
            int tl = s >> 9, rem = s & 511;
            int r = rem >> 3, cg = rem & 7;
            size_t off = (rowbase + kc + r)*(size_t)NQKV + h*DNN + cg*8;
            const __half* src = qvh + off + (tl ? 2*DD : DD);
            CP_ASYNC(smem_u32(base + tl*9216 + r*144 + cg*16), src);
        }
#pragma unroll
        for (int i = 0; i < 2; i++) {
            int s = tid + i*256;
            int r = s >> 2, seg = s & 3;
            CP_ASYNC(smem_u32(base + AT_MS + r*64 + seg*16),
                     mask8 + (rowbase + sq0 + r)*(size_t)SS + kc + seg*16);
        }
        CP_COMMIT();
    };

    load_kv(0, 0);

    uint32_t qfh[4][4];
    float o[8][4];
#pragma unroll
    for (int nt = 0; nt < 8; nt++)
#pragma unroll
        for (int q = 0; q < 4; q++) o[nt][q] = 0.f;
    float rs0 = 0.f, rs1 = 0.f;

    for (int ci = 0; ci < 8; ci++) {
        int st = ci & 1;
        CP_WAIT0();
        __syncthreads();
        if (ci == 0) {
            uint32_t qb = smem_u32(smn);
#pragma unroll
            for (int kg = 0; kg < 4; kg++) {
                uint32_t qa = qb + (wid*16 + l15)*144 + kg*32 + (lid >> 4)*16;
                LDSM4(qfh[kg], qa);
            }
        }
        if (ci + 1 < 8) load_kv(ci + 1, st ^ 1);

        uint32_t sb = smem_u32(smn + AT_ST0 + st*AT_STAGE);
        const unsigned char* msm = (const unsigned char*)(smn + AT_ST0 + st*AT_STAGE + AT_MS);

#pragma unroll
        for (int h2 = 0; h2 < 2; h2++) {
            int rof = h2 * 32;
            float s[4][4];
#pragma unroll
            for (int nt = 0; nt < 4; nt++)
#pragma unroll
                for (int q = 0; q < 4; q++) s[nt][q] = 0.f;

            // S = Q K^T (single plane)
#pragma unroll
            for (int kg = 0; kg < 4; kg++) {
#pragma unroll
                for (int nt = 0; nt < 4; nt += 2) {
                    uint32_t t4[4];
                    uint32_t ka = sb + (rof + (nt + qq)*8 + l8)*144 + kg*32 + selK*16;
                    LDSM4(t4, ka + AT_KH);
                    uint32_t b0[2] = {t4[0], t4[1]};
                    uint32_t b1[2] = {t4[2], t4[3]};
                    MMA16816(s[nt],   qfh[kg], b0);
                    MMA16816(s[nt+1], qfh[kg], b1);
                }
            }

            // softmax numerator + pack P (single plane)
            const unsigned char* mr0 = msm + (wid*16 + g)*64 + rof;
            const unsigned char* mr1 = mr0 + 8*64;
            uint32_t aPh[2][4];
#pragma unroll
            for (int nt = 0; nt < 4; nt++) {
                uchar2 m0 = *(const uchar2*)(mr0 + nt*8 + t2*2);
                uchar2 m1 = *(const uchar2*)(mr1 + nt*8 + t2*2);
                float p0 = m0.x ? 0.f : fexp(s[nt][0]*0.125f);
                float p1 = m0.y ? 0.f : fexp(s[nt][1]*0.125f);
                float p2 = m1.x ? 0.f : fexp(s[nt][2]*0.125f);
                float p3 = m1.y ? 0.f : fexp(s[nt][3]*0.125f);
                rs0 += p0 + p1;
                rs1 += p2 + p3;
                int kg = nt >> 1, sub = (nt & 1)*2;
                __half2 h01 = __floats2half2_rn(p0, p1);
                __half2 h23 = __floats2half2_rn(p2, p3);
                aPh[kg][sub]   = *(uint32_t*)&h01;
                aPh[kg][sub+1] = *(uint32_t*)&h23;
            }

            // O += P V (single plane)
#pragma unroll
            for (int kg = 0; kg < 2; kg++) {
#pragma unroll
                for (int nt = 0; nt < 8; nt += 2) {
                    uint32_t t4[4];
                    uint32_t va = sb + AT_VH + (rof + kg*16 + l15)*144 + (nt + qq)*16;
                    LDSM4T(t4, va);
                    uint32_t v0[2] = {t4[0], t4[1]};
                    uint32_t v1[2] = {t4[2], t4[3]};
                    MMA16816(o[nt],   aPh[kg], v0);
                    MMA16816(o[nt+1], aPh[kg], v1);
                }
            }
        }
    }

    rs0 += __shfl_xor_sync(0xFFFFFFFFu, rs0, 1);
    rs0 += __shfl_xor_sync(0xFFFFFFFFu, rs0, 2);
    rs1 += __shfl_xor_sync(0xFFFFFFFFu, rs1, 1);
    rs1 += __shfl_xor_sync(0xFFFFFFFFu, rs1, 2);
    float inv0 = 1.f / rs0, inv1 = 1.f / rs1;

    long r0 = rowbase + sq0 + wid*16 + g;
    int colb = h*DNN + t2*2;
#pragma unroll
    for (int nt = 0; nt < 8; nt++) {
        int col = colb + nt*8;
        uint32_t hp0, lp0, hp1, lp1;
        hsplit2(o[nt][0]*inv0, o[nt][1]*inv0, hp0, lp0);
        hsplit2(o[nt][2]*inv1, o[nt][3]*inv1, hp1, lp1);
        *(uint32_t*)(ohi + r0*DD + col)     = hp0;
        *(uint32_t*)(olo + r0*DD + col)     = lp0;
        *(uint32_t*)(ohi + (r0+8)*DD + col) = hp1;
        *(uint32_t*)(olo + (r0+8)*DD + col) = lp1;
    }
}

// ---------------- fused split-K-reduce + layernorm (warp-per-row) ----------------
__global__ void __launch_bounds__(256)
ln2_kernel(const float* __restrict__ p1, const float* __restrict__ p2,
           const float* __restrict__ res, const float* __restrict__ bias,
           const float* __restrict__ g, const float* __restrict__ be,
           float* __restrict__ out,
           __half* __restrict__ ohi, __half* __restrict__ olo)
{
    int row = blockIdx.x*8 + (threadIdx.x >> 5);
    int lane = threadIdx.x & 31;
    size_t base = (size_t)row*DD;

    float v[24];
    float s = 0.f, sq = 0.f;
#pragma unroll
    for (int i = 0; i < 6; i++) {
        int col = lane*4 + i*128;
        float4 a  = *(const float4*)(p1  + base + col);
        float4 b  = *(const float4*)(p2  + base + col);
        float4 r  = *(const float4*)(res + base + col);
        float4 bi = *(const float4*)(bias + col);
        float x0 = a.x + b.x + r.x + bi.x;
        float x1 = a.y + b.y + r.y + bi.y;
        float x2 = a.z + b.z + r.z + bi.z;
        float x3 = a.w + b.w + r.w + bi.w;
        v[i*4+0]=x0; v[i*4+1]=x1; v[i*4+2]=x2; v[i*4+3]=x3;
        s += (x0+x1) + (x2+x3);
        sq += (x0*x0 + x1*x1) + (x2*x2 + x3*x3);
    }
#pragma unroll
    for (int o = 16; o > 0; o >>= 1) {
        s  += __shfl_xor_sync(0xFFFFFFFFu, s,  o);
        sq += __shfl_xor_sync(0xFFFFFFFFu, sq, o);
    }
    float mean = s * (1.0f/768.0f);
    float var  = sq * (1.0f/768.0f) - mean*mean;
    float rstd = rsqrtf(var + 1e-5f);

#pragma unroll
    for (int i = 0; i < 6; i++) {
        int col = lane*4 + i*128;
        float4 gg = *(const float4*)(g  + col);
        float4 bb = *(const float4*)(be + col);
        float y0 = (v[i*4+0]-mean)*rstd*gg.x + bb.x;
        float y1 = (v[i*4+1]-mean)*rstd*gg.y + bb.y;
        float y2 = (v[i*4+2]-mean)*rstd*gg.z + bb.z;
        float y3 = (v[i*4+3]-mean)*rstd*gg.w + bb.w;
        *(float4*)(out + base + col) = make_float4(y0, y1, y2, y3);
        uint2 hp, lp;
        hsplit2(y0, y1, hp.x, lp.x);
        hsplit2(y2, y3, hp.y, lp.y);
        *(uint2*)(ohi + base + col) = hp;
        *(uint2*)(olo + base + col) = lp;
    }
}

// ---------------- host ----------------
extern "C" void kernel_launch(void* const* d_in, const int* in_sizes, int n_in,
                              void* d_out, int out_size)
{
    const int*   x    = (const int*)  d_in[0];
    const int*   pmsk = (const int*)  d_in[1];
    const float* emb  = (const float*)d_in[2];
    const float* Wq   = (const float*)d_in[3];
    const float* bq   = (const float*)d_in[4];
    const float* Wk   = (const float*)d_in[5];
    const float* bk   = (const float*)d_in[6];
    const float* Wv   = (const float*)d_in[7];
    const float* bv   = (const float*)d_in[8];
    const float* Wo   = (const float*)d_in[9];
    const float* bo   = (const float*)d_in[10];
    const float* W1   = (const float*)d_in[11];
    const float* b1   = (const float*)d_in[12];
    const float* W2   = (const float*)d_in[13];
    const float* b2   = (const float*)d_in[14];
    const float* g1   = (const float*)d_in[15];
    const float* be1  = (const float*)d_in[16];
    const float* g2   = (const float*)d_in[17];
    const float* be2  = (const float*)d_in[18];
    float* outp = (float*)d_out;

    float *hb, *tb, *tb2;
    __half *hhi, *hlo, *qkvh, *ohi, *olo, *fhi, *flo, *wh;
    unsigned char* m8;
    cudaGetSymbolAddress((void**)&hb,    g_h);
    cudaGetSymbolAddress((void**)&tb,    g_t);
    cudaGetSymbolAddress((void**)&tb2,   g_t2);
    cudaGetSymbolAddress((void**)&hhi,   g_hhi);
    cudaGetSymbolAddress((void**)&hlo,   g_hlo);
    cudaGetSymbolAddress((void**)&qkvh,  g_qkvh);
    cudaGetSymbolAddress((void**)&ohi,   g_ohi);
    cudaGetSymbolAddress((void**)&olo,   g_olo);
    cudaGetSymbolAddress((void**)&fhi,   g_fhi);
    cudaGetSymbolAddress((void**)&flo,   g_flo);
    cudaGetSymbolAddress((void**)&wh,    g_Wh);
    cudaGetSymbolAddress((void**)&m8,    g_mask8);

    cudaFuncSetAttribute(gemm_mma<1>, cudaFuncAttributeMaxDynamicSharedMemorySize, GEMM_SMEM);
    cudaFuncSetAttribute(gemm_mma<3>, cudaFuncAttributeMaxDynamicSharedMemorySize, GEMM_SMEM);
    cudaFuncSetAttribute(gemm_mma<4>, cudaFuncAttributeMaxDynamicSharedMemorySize, GEMM_SMEM);
    cudaFuncSetAttribute(attn_mma,    cudaFuncAttributeMaxDynamicSharedMemorySize, AT_SMEM);

    dim3 gQKV(NQKV/128, MM/128);
    dim3 gSplit(DD/128, MM/128, 2);
    dim3 gF1 (FF/128,   MM/128);
    dim3 gAttn(BB*HH, SS/128);

    tsplit_qkv<<<dim3(2, 24, LL*36), 256>>>(Wq, Wk, Wv);
    embed_mask_kernel<<<EMBED_BLKS + MASK_BLKS, 256>>>(x, emb, pmsk);

    for (int l = 0; l < LL; l++) {
        const __half* wl = wh + (size_t)l*LAYER_SZ;

        gemm_mma<3><<<gQKV, 256, GEMM_SMEM>>>(hhi, hlo, wl,
            bq + l*DD, bk + l*DD, bv + l*DD,
            nullptr, nullptr, qkvh, nullptr, DD, NQKV);

        attn_mma<<<gAttn, 256, AT_SMEM>>>(qkvh, m8, ohi, olo);

        if (l == 0)
            tsplit<<<dim3(24, 24, LL), 256>>>(Wo, wh + OFF_O,
                DD, DD, (size_t)DD*DD, (size_t)LAYER_SZ);

        gemm_mma<4><<<gSplit, 256, GEMM_SMEM>>>(ohi, olo, wl + OFF_O,
            nullptr, nullptr, nullptr, tb, tb2, nullptr, nullptr, DD, DD);

        ln2_kernel<<<MM/8, 256>>>(tb, tb2, hb, bo + l*DD,
                                  g1 + l*DD, be1 + l*DD, hb, hhi, hlo);

        if (l == 0)
            tsplit<<<dim3(96, 24, LL), 256>>>(W1, wh + OFF_W1,
                DD, FF, (size_t)DD*FF, (size_t)LAYER_SZ);

        gemm_mma<1><<<gF1, 256, GEMM_SMEM>>>(hhi, hlo, wl + OFF_W1,
            b1 + l*FF, nullptr, nullptr, nullptr, nullptr, fhi, flo, DD, FF);

        if (l == 0)
            tsplit<<<dim3(24, 96, LL), 256>>>(W2, wh + OFF_W2,
                FF, DD, (size_t)FF*DD, (size_t)LAYER_SZ);

        gemm_mma<4><<<gSplit, 256, GEMM_SMEM>>>(fhi, flo, wl + OFF_W2,
            nullptr, nullptr, nullptr, tb, tb2, nullptr, nullptr, FF, DD);

        float* lnOut = (l == LL-1) ? outp : hb;
        ln2_kernel<<<MM/8, 256>>>(tb, tb2, hb, b2 + l*DD,
                                  g2 + l*DD, be2 + l*DD, lnOut, hhi, hlo);
    }
}